// round 3
// baseline (speedup 1.0000x reference)
#include <cuda_runtime.h>
#include <cuda_bf16.h>

#define NN 1024
#define HID 256
#define NH 8
#define HD 32
#define NE 16384

// ---------------- scratch (static device memory; no allocations) -------------
__device__ float    g_q[NN * HID];
__device__ float    g_k[NN * HID];
__device__ float    g_v[NN * HID];
__device__ float    g_concat[NN * 2 * HID];
__device__ float    g_gateh[NN * 4 * HID];
__device__ float    g_gate[NN * 2];
__device__ unsigned g_adj[NN * 32];
__device__ unsigned g_pa[NN * 32];
__device__ unsigned g_pb[NN * 32];
__device__ float    g_ttab[16];            // [path_val(0/1)][head]
__device__ float    g_logits[NN * NH * NN];   // 32 MB, [n][h][m]
__device__ float    g_attnout[NN * HID];
__device__ float    g_proj[NN * HID];
__device__ int      g_idx64;

// ---------------- edge index dtype detection ---------------------------------
// Values are in [0,1024). If stored as little-endian int64, every odd 32-bit
// word of the first 64 entries is 0. If int32, those words are uniform random
// indices (all-zero probability ~0).
__global__ void detect_kernel(const unsigned* __restrict__ w) {
    if (threadIdx.x == 0) {
        int is64 = 1;
        for (int i = 0; i < 64; i++) {
            if (w[2 * i + 1] != 0u) { is64 = 0; break; }
        }
        g_idx64 = is64;
    }
}

__global__ void zero_adj_kernel() {
    int i = blockIdx.x * 256 + threadIdx.x;
    if (i < NN * 32) g_adj[i] = 0u;
}

__global__ void scatter_edges_kernel(const void* __restrict__ edges) {
    int e = blockIdx.x * blockDim.x + threadIdx.x;
    if (e >= NE) return;
    int s, d;
    if (g_idx64) {
        const long long* p = (const long long*)edges;
        s = (int)p[e];
        d = (int)p[NE + e];
    } else {
        const int* p = (const int*)edges;
        s = p[e];
        d = p[NE + e];
    }
    atomicOr(&g_adj[s * 32 + (d >> 5)], 1u << (d & 31));
}

// path = min(path, path @ adj): binary matrices -> bitset reachability step.
// new_row[i] = old_row[i] AND (OR_{k in old_row[i]} adj_row[k])
__global__ void path_round_kernel(int r) {
    const unsigned* in = (r == 0) ? g_adj : ((r == 1) ? g_pa : g_pb);
    unsigned* out = (r == 1) ? g_pb : g_pa;
    int row = blockIdx.x, lane = threadIdx.x;
    __shared__ unsigned irow[32];
    irow[lane] = in[row * 32 + lane];
    __syncwarp();
    unsigned acc = 0u;
    for (int w = 0; w < 32; w++) {
        unsigned word = irow[w];
        while (word) {
            int b = __ffs(word) - 1;
            word &= word - 1;
            acc |= g_adj[(w * 32 + b) * 32 + lane];
        }
    }
    out[row * 32 + lane] = irow[lane] & acc;
}

// topo bias only depends on path bit in {0,1}: table [2][8]
__global__ void ttab_kernel(const float* __restrict__ w1, const float* __restrict__ b1,
                            const float* __restrict__ w2, const float* __restrict__ b2) {
    int t = threadIdx.x;
    if (t < 16) {
        float pv = (float)(t >> 3);
        int h = t & 7;
        float acc = b2[h];
        for (int c = 0; c < 32; c++) {
            float hv = fmaf(pv, w1[c], b1[c]);
            float s = __fdividef(hv, 1.f + __expf(-hv));   // silu
            acc = fmaf(s, w2[c * 8 + h], acc);
        }
        g_ttab[t] = acc;
    }
}

// ---------------- generic 64x64 tiled SGEMM, C = A@B + bias [, silu] ---------
__global__ __launch_bounds__(256) void sgemm64(
    const float* __restrict__ A, int lda,
    const float* __restrict__ B, int ldb,
    const float* __restrict__ bias,
    float* __restrict__ C, int ldc, int K, int act)
{
    __shared__ float As[16][68];
    __shared__ float Bs[16][64];
    int tid = threadIdx.x;
    int tx = tid & 15, ty = tid >> 4;
    int row0 = blockIdx.y * 64, col0 = blockIdx.x * 64;
    float acc[4][4];
#pragma unroll
    for (int i = 0; i < 4; i++)
#pragma unroll
        for (int j = 0; j < 4; j++) acc[i][j] = 0.f;
    int ar = tid >> 2, ac = (tid & 3) << 2;
    int bk = tid >> 4, bn = (tid & 15) << 2;
    for (int k0 = 0; k0 < K; k0 += 16) {
        float4 av = *(const float4*)&A[(row0 + ar) * lda + k0 + ac];
        As[ac + 0][ar] = av.x; As[ac + 1][ar] = av.y;
        As[ac + 2][ar] = av.z; As[ac + 3][ar] = av.w;
        *(float4*)&Bs[bk][bn] = *(const float4*)&B[(k0 + bk) * ldb + col0 + bn];
        __syncthreads();
#pragma unroll
        for (int kk = 0; kk < 16; kk++) {
            float4 a = *(const float4*)&As[kk][ty << 2];
            float4 b = *(const float4*)&Bs[kk][tx << 2];
            acc[0][0] = fmaf(a.x, b.x, acc[0][0]); acc[0][1] = fmaf(a.x, b.y, acc[0][1]);
            acc[0][2] = fmaf(a.x, b.z, acc[0][2]); acc[0][3] = fmaf(a.x, b.w, acc[0][3]);
            acc[1][0] = fmaf(a.y, b.x, acc[1][0]); acc[1][1] = fmaf(a.y, b.y, acc[1][1]);
            acc[1][2] = fmaf(a.y, b.z, acc[1][2]); acc[1][3] = fmaf(a.y, b.w, acc[1][3]);
            acc[2][0] = fmaf(a.z, b.x, acc[2][0]); acc[2][1] = fmaf(a.z, b.y, acc[2][1]);
            acc[2][2] = fmaf(a.z, b.z, acc[2][2]); acc[2][3] = fmaf(a.z, b.w, acc[2][3]);
            acc[3][0] = fmaf(a.w, b.x, acc[3][0]); acc[3][1] = fmaf(a.w, b.y, acc[3][1]);
            acc[3][2] = fmaf(a.w, b.z, acc[3][2]); acc[3][3] = fmaf(a.w, b.w, acc[3][3]);
        }
        __syncthreads();
    }
#pragma unroll
    for (int i = 0; i < 4; i++) {
        int r = row0 + (ty << 2) + i;
#pragma unroll
        for (int j = 0; j < 4; j++) {
            int c = col0 + (tx << 2) + j;
            float v = acc[i][j] + bias[c];
            if (act) v = __fdividef(v, 1.f + __expf(-v));  // silu
            C[r * ldc + c] = v;
        }
    }
}

__global__ void concat_kernel(const float* __restrict__ src, const float* __restrict__ tgt) {
    int i = blockIdx.x * 256 + threadIdx.x;     // 1024*512 total
    int n = i >> 9, c = i & 511;
    g_concat[i] = (c < 256) ? src[n * 256 + c] : tgt[n * 256 + (c - 256)];
}

// gate logits: 2 dots of length 1024 per node, then 2-way softmax
__global__ __launch_bounds__(256) void gate2_kernel(const float* __restrict__ w2,
                                                    const float* __restrict__ b2) {
    int n = blockIdx.x, tid = threadIdx.x;
    const float* hrow = g_gateh + n * 1024;
    float s0 = 0.f, s1 = 0.f;
#pragma unroll
    for (int t = 0; t < 4; t++) {
        int j = tid + 256 * t;
        float hv = hrow[j];
        s0 = fmaf(hv, w2[j * 2 + 0], s0);
        s1 = fmaf(hv, w2[j * 2 + 1], s1);
    }
    for (int o = 16; o; o >>= 1) {
        s0 += __shfl_xor_sync(~0u, s0, o);
        s1 += __shfl_xor_sync(~0u, s1, o);
    }
    __shared__ float r0[8], r1[8];
    if ((tid & 31) == 0) { r0[tid >> 5] = s0; r1[tid >> 5] = s1; }
    __syncthreads();
    if (tid == 0) {
        float l0 = b2[0], l1 = b2[1];
        for (int j = 0; j < 8; j++) { l0 += r0[j]; l1 += r1[j]; }
        float m = fmaxf(l0, l1);
        float e0 = __expf(l0 - m), e1 = __expf(l1 - m);
        float inv = __fdividef(1.f, e0 + e1);
        g_gate[n * 2 + 0] = e0 * inv;
        g_gate[n * 2 + 1] = e1 * inv;
    }
}

// ---------------- fused logits: QK/sqrt(D) + gate0*geoMLP(dist) + gate1*topo -
#define QPAD 260
#define LOGITS_SMEM ((64 * QPAD + 600 + 32) * 4)

__global__ __launch_bounds__(256) void logits_kernel(
    const float* __restrict__ pos,
    const float* __restrict__ gw1, const float* __restrict__ gb1,
    const float* __restrict__ gw2, const float* __restrict__ gb2)
{
    extern __shared__ float sh[];
    float* qs  = sh;                     // 32 x 260
    float* ks  = sh + 32 * QPAD;         // 32 x 260
    float* ext = sh + 64 * QPAD;
    float* sw1 = ext;                    // 32
    float* sb1 = sw1 + 32;               // 32
    float* sw2 = sb1 + 32;               // 256 [c*8+h]
    float* sb2 = sw2 + 256;              // 8
    float* sg0 = sb2 + 8;                // 32
    float* sg1 = sg0 + 32;               // 32
    float* spn = sg1 + 32;               // 32*3
    float* spm = spn + 96;               // 32*3
    float* stt = spm + 96;               // 16
    unsigned* spw = (unsigned*)(stt + 16); // 32

    int tid = threadIdx.x;
    int m0 = blockIdx.x * 32, n0 = blockIdx.y * 32;

#pragma unroll
    for (int t = 0; t < 8; t++) {
        int lin = tid + 256 * t;         // float4 index, 2048 total
        int r = lin >> 6, c4 = (lin & 63) << 2;
        *(float4*)&qs[r * QPAD + c4] = *(const float4*)&g_q[(n0 + r) * 256 + c4];
        *(float4*)&ks[r * QPAD + c4] = *(const float4*)&g_k[(m0 + r) * 256 + c4];
    }
    if (tid < 32) {
        sw1[tid] = gw1[tid]; sb1[tid] = gb1[tid];
        sg0[tid] = g_gate[(n0 + tid) * 2 + 0];
        sg1[tid] = g_gate[(n0 + tid) * 2 + 1];
        spw[tid] = g_pa[(n0 + tid) * 32 + blockIdx.x];
        spn[tid * 3 + 0] = pos[(n0 + tid) * 3 + 0];
        spn[tid * 3 + 1] = pos[(n0 + tid) * 3 + 1];
        spn[tid * 3 + 2] = pos[(n0 + tid) * 3 + 2];
        spm[tid * 3 + 0] = pos[(m0 + tid) * 3 + 0];
        spm[tid * 3 + 1] = pos[(m0 + tid) * 3 + 1];
        spm[tid * 3 + 2] = pos[(m0 + tid) * 3 + 2];
    }
    if (tid < 256) sw2[tid] = gw2[tid];
    if (tid < 8)  sb2[tid] = gb2[tid];
    if (tid < 16) stt[tid] = g_ttab[tid];
    __syncthreads();

    int mi = tid & 31, nbase = tid >> 5;   // lane = m, warp = n-group
    float res[4][8];
    float px = spm[mi * 3 + 0], py = spm[mi * 3 + 1], pz = spm[mi * 3 + 2];

#pragma unroll
    for (int i = 0; i < 4; i++) {
        int ni = nbase + 8 * i;
        float dx = spn[ni * 3 + 0] - px;
        float dy = spn[ni * 3 + 1] - py;
        float dz = spn[ni * 3 + 2] - pz;
        float dist = sqrtf(fmaxf(dx * dx + dy * dy + dz * dz, 1e-12f));
        float gv0 = sg0[ni], gv1 = sg1[ni];
        int bit = (spw[ni] >> mi) & 1;
        float a[8];
#pragma unroll
        for (int h = 0; h < 8; h++) a[h] = sb2[h];
#pragma unroll
        for (int c = 0; c < 32; c++) {
            float hv = fmaf(dist, sw1[c], sb1[c]);
            float s = __fdividef(hv, 1.f + __expf(-hv));   // silu
#pragma unroll
            for (int h = 0; h < 8; h++) a[h] = fmaf(s, sw2[c * 8 + h], a[h]);
        }
#pragma unroll
        for (int h = 0; h < 8; h++)
            res[i][h] = gv0 * a[h] + gv1 * stt[bit * 8 + h];
    }

    const float scale = 0.17677669529663687f;   // 1/sqrt(32)
#pragma unroll
    for (int h = 0; h < 8; h++) {
        float4 kr[8];
#pragma unroll
        for (int j = 0; j < 8; j++)
            kr[j] = *(const float4*)&ks[mi * QPAD + h * 32 + j * 4];
#pragma unroll
        for (int i = 0; i < 4; i++) {
            int ni = nbase + 8 * i;
            float s = 0.f;
#pragma unroll
            for (int j = 0; j < 8; j++) {
                float4 qv = *(const float4*)&qs[ni * QPAD + h * 32 + j * 4];
                s += qv.x * kr[j].x + qv.y * kr[j].y + qv.z * kr[j].z + qv.w * kr[j].w;
            }
            res[i][h] = fmaf(s, scale, res[i][h]);
        }
    }

#pragma unroll
    for (int i = 0; i < 4; i++) {
        int ng = n0 + nbase + 8 * i;
#pragma unroll
        for (int h = 0; h < 8; h++)
            g_logits[(ng * 8 + h) * 1024 + m0 + mi] = res[i][h];
    }
}

// ---------------- softmax over m, row = n*8+h ---------------------------------
__global__ __launch_bounds__(256) void softmax_kernel() {
    int row = blockIdx.x;
    float* p = g_logits + (long)row * 1024;
    int tid = threadIdx.x;
    float4 v = *(float4*)&p[tid * 4];
    float mx = fmaxf(fmaxf(v.x, v.y), fmaxf(v.z, v.w));
    for (int o = 16; o; o >>= 1) mx = fmaxf(mx, __shfl_xor_sync(~0u, mx, o));
    __shared__ float rm[8], rs[8];
    if ((tid & 31) == 0) rm[tid >> 5] = mx;
    __syncthreads();
    mx = rm[0];
#pragma unroll
    for (int j = 1; j < 8; j++) mx = fmaxf(mx, rm[j]);
    v.x = __expf(v.x - mx); v.y = __expf(v.y - mx);
    v.z = __expf(v.z - mx); v.w = __expf(v.w - mx);
    float s = v.x + v.y + v.z + v.w;
    for (int o = 16; o; o >>= 1) s += __shfl_xor_sync(~0u, s, o);
    if ((tid & 31) == 0) rs[tid >> 5] = s;
    __syncthreads();
    s = 0.f;
#pragma unroll
    for (int j = 0; j < 8; j++) s += rs[j];
    float inv = __fdividef(1.f, s);
    v.x *= inv; v.y *= inv; v.z *= inv; v.w *= inv;
    *(float4*)&p[tid * 4] = v;
}

// ---------------- PV: out[n, h*32+d] = sum_m attn[n,h,m] v[m, h*32+d] --------
__global__ __launch_bounds__(256) void pv_kernel() {
    int h = blockIdx.x, n0 = blockIdx.y * 64;
    __shared__ float As[64][36];   // n x m
    __shared__ float Bs[32][32];   // m x d
    int tid = threadIdx.x;
    int dxi = tid & 31;            // d
    int ty = tid >> 5;             // 0..7 (n row group)
    float acc[8];
#pragma unroll
    for (int i = 0; i < 8; i++) acc[i] = 0.f;

    for (int m0 = 0; m0 < 1024; m0 += 32) {
#pragma unroll
        for (int t = 0; t < 2; t++) {
            int lin = tid + 256 * t;
            int r = lin >> 3, c4 = (lin & 7) << 2;
            *(float4*)&As[r][c4] =
                *(const float4*)&g_logits[((long)(n0 + r) * 8 + h) * 1024 + m0 + c4];
        }
        {
            int r = tid >> 3, c4 = (tid & 7) << 2;
            *(float4*)&Bs[r][c4] = *(const float4*)&g_v[(m0 + r) * 256 + h * 32 + c4];
        }
        __syncthreads();
#pragma unroll
        for (int mm = 0; mm < 32; mm += 4) {
            float b0 = Bs[mm + 0][dxi], b1 = Bs[mm + 1][dxi];
            float b2 = Bs[mm + 2][dxi], b3 = Bs[mm + 3][dxi];
#pragma unroll
            for (int i = 0; i < 8; i++) {
                float4 a = *(const float4*)&As[ty + 8 * i][mm];
                acc[i] = fmaf(a.x, b0, fmaf(a.y, b1, fmaf(a.z, b2, fmaf(a.w, b3, acc[i]))));
            }
        }
        __syncthreads();
    }
#pragma unroll
    for (int i = 0; i < 8; i++)
        g_attnout[(n0 + ty + 8 * i) * 256 + h * 32 + dxi] = acc[i];
}

// ---------------- residual + layernorm ----------------------------------------
__global__ __launch_bounds__(256) void ln_kernel(const float* __restrict__ src,
                                                 const float* __restrict__ g,
                                                 const float* __restrict__ b,
                                                 float* __restrict__ out) {
    int n = blockIdx.x, tid = threadIdx.x;
    float x = src[n * 256 + tid] + g_proj[n * 256 + tid];
    float s = x;
    for (int o = 16; o; o >>= 1) s += __shfl_xor_sync(~0u, s, o);
    __shared__ float r1[8], r2[8];
    if ((tid & 31) == 0) r1[tid >> 5] = s;
    __syncthreads();
    float tot = 0.f;
#pragma unroll
    for (int j = 0; j < 8; j++) tot += r1[j];
    float mu = tot * (1.f / 256.f);
    float d = x - mu;
    float s2 = d * d;
    for (int o = 16; o; o >>= 1) s2 += __shfl_xor_sync(~0u, s2, o);
    if ((tid & 31) == 0) r2[tid >> 5] = s2;
    __syncthreads();
    float var = 0.f;
#pragma unroll
    for (int j = 0; j < 8; j++) var += r2[j];
    var *= (1.f / 256.f);
    out[n * 256 + tid] = d * rsqrtf(var + 1e-5f) * g[tid] + b[tid];
}

// ---------------- launch ------------------------------------------------------
extern "C" void kernel_launch(void* const* d_in, const int* in_sizes, int n_in,
                              void* d_out, int out_size) {
    const float* src_feat = (const float*)d_in[0];
    const float* tgt_feat = (const float*)d_in[1];
    const float* src_pos  = (const float*)d_in[2];
    const void*  edges    = d_in[3];
    const float* Wq = (const float*)d_in[4],  *bq = (const float*)d_in[5];
    const float* Wk = (const float*)d_in[6],  *bk = (const float*)d_in[7];
    const float* Wv = (const float*)d_in[8],  *bv = (const float*)d_in[9];
    const float* geo_w1 = (const float*)d_in[10], *geo_b1 = (const float*)d_in[11];
    const float* geo_w2 = (const float*)d_in[12], *geo_b2 = (const float*)d_in[13];
    const float* top_w1 = (const float*)d_in[14], *top_b1 = (const float*)d_in[15];
    const float* top_w2 = (const float*)d_in[16], *top_b2 = (const float*)d_in[17];
    const float* gate_w1 = (const float*)d_in[18], *gate_b1 = (const float*)d_in[19];
    const float* gate_w2 = (const float*)d_in[20], *gate_b2 = (const float*)d_in[21];
    const float* Wo = (const float*)d_in[22], *bo = (const float*)d_in[23];
    const float* ln_g = (const float*)d_in[24], *ln_b = (const float*)d_in[25];
    float* out = (float*)d_out;

    void *pq, *pk, *pv, *pconcat, *pgateh, *pattn, *pproj;
    cudaGetSymbolAddress(&pq, g_q);
    cudaGetSymbolAddress(&pk, g_k);
    cudaGetSymbolAddress(&pv, g_v);
    cudaGetSymbolAddress(&pconcat, g_concat);
    cudaGetSymbolAddress(&pgateh, g_gateh);
    cudaGetSymbolAddress(&pattn, g_attnout);
    cudaGetSymbolAddress(&pproj, g_proj);

    cudaFuncSetAttribute(logits_kernel,
                         cudaFuncAttributeMaxDynamicSharedMemorySize, LOGITS_SMEM);

    // adjacency / path propagation (binary bitsets)
    detect_kernel<<<1, 1>>>((const unsigned*)edges);
    zero_adj_kernel<<<128, 256>>>();
    scatter_edges_kernel<<<64, 256>>>(edges);
    path_round_kernel<<<1024, 32>>>(0);
    path_round_kernel<<<1024, 32>>>(1);
    path_round_kernel<<<1024, 32>>>(2);   // final path in g_pa
    ttab_kernel<<<1, 16>>>(top_w1, top_b1, top_w2, top_b2);

    // q/k/v projections
    sgemm64<<<dim3(4, 16), 256>>>(src_feat, 256, Wq, 256, bq, (float*)pq, 256, 256, 0);
    sgemm64<<<dim3(4, 16), 256>>>(tgt_feat, 256, Wk, 256, bk, (float*)pk, 256, 256, 0);
    sgemm64<<<dim3(4, 16), 256>>>(tgt_feat, 256, Wv, 256, bv, (float*)pv, 256, 256, 0);

    // gate MLP
    concat_kernel<<<2048, 256>>>(src_feat, tgt_feat);
    sgemm64<<<dim3(16, 16), 256>>>((const float*)pconcat, 512, gate_w1, 1024, gate_b1,
                                   (float*)pgateh, 1024, 512, 1);
    gate2_kernel<<<1024, 256>>>(gate_w2, gate_b2);

    // fused QK + geo + topo logits, softmax, PV
    logits_kernel<<<dim3(32, 32), 256, LOGITS_SMEM>>>(src_pos, geo_w1, geo_b1, geo_w2, geo_b2);
    softmax_kernel<<<8192, 256>>>();
    pv_kernel<<<dim3(8, 16), 256>>>();

    // output projection + residual + layernorm
    sgemm64<<<dim3(4, 16), 256>>>((const float*)pattn, 256, Wo, 256, bo,
                                  (float*)pproj, 256, 256, 0);
    ln_kernel<<<1024, 256>>>(src_feat, ln_g, ln_b, out);
}

// round 4
// speedup vs baseline: 1.3754x; 1.3754x over previous
#include <cuda_runtime.h>
#include <cuda_bf16.h>

#define NN 1024
#define HID 256
#define NH 8
#define HD 32
#define NE 16384

#define TBL_N 8192
#define TBL_MAX 24.0f
#define TBL_SCALE ((float)(TBL_N - 1) / TBL_MAX)

// ---------------- scratch (static device memory; no allocations) -------------
__device__ float    g_q[NN * HID];
__device__ float    g_k[NN * HID];
__device__ float    g_v[NN * HID];
__device__ float    g_gateh[NN * 4 * HID];
__device__ float    g_gate[NN * 2];
__device__ unsigned g_adj[NN * 32];
__device__ unsigned g_pa[NN * 32];
__device__ unsigned g_pb[NN * 32];
__device__ float    g_ttab[16];                  // [path_val(0/1)][head]
__device__ float    g_tbl[TBL_N * 8];            // geo MLP lookup table [i][h]
__device__ float    g_logits[NN * NH * NN];      // 32 MB, [n][h][m], raw logits
__device__ float2   g_stats[NN * NH];            // per-row (max, 1/sum)
__device__ float    g_attnout[NN * HID];
__device__ float    g_proj[NN * HID];
__device__ int      g_idx64;

// ---------------- edge index dtype detection ---------------------------------
__global__ void detect_kernel(const unsigned* __restrict__ w) {
    if (threadIdx.x == 0) {
        int is64 = 1;
        for (int i = 0; i < 64; i++) {
            if (w[2 * i + 1] != 0u) { is64 = 0; break; }
        }
        g_idx64 = is64;
    }
}

__global__ void zero_adj_kernel() {
    int i = blockIdx.x * 256 + threadIdx.x;
    if (i < NN * 32) g_adj[i] = 0u;
}

__global__ void scatter_edges_kernel(const void* __restrict__ edges) {
    int e = blockIdx.x * blockDim.x + threadIdx.x;
    if (e >= NE) return;
    int s, d;
    if (g_idx64) {
        const long long* p = (const long long*)edges;
        s = (int)p[e];
        d = (int)p[NE + e];
    } else {
        const int* p = (const int*)edges;
        s = p[e];
        d = p[NE + e];
    }
    atomicOr(&g_adj[s * 32 + (d >> 5)], 1u << (d & 31));
}

// path = min(path, path @ adj): binary reachability step on bitsets.
// new_row[i] = old_row[i] AND (OR_{k in old_row[i]} adj_row[k])
// 8 warps/block, one row per warp; set-bit indices extracted to smem so the
// OR-gather runs with MLP=4 independent loads.
#define LIST_CAP 512
__global__ __launch_bounds__(256) void path_round_kernel(int r) {
    const unsigned* in = (r == 0) ? g_adj : ((r == 1) ? g_pa : g_pb);
    unsigned* out = (r == 1) ? g_pb : g_pa;
    __shared__ unsigned short lists[8][LIST_CAP];
    int warp = threadIdx.x >> 5, lane = threadIdx.x & 31;
    int row = blockIdx.x * 8 + warp;
    unsigned w = in[row * 32 + lane];
    int c = __popc(w);
    int pre = c;
#pragma unroll
    for (int o = 1; o < 32; o <<= 1) {
        int x = __shfl_up_sync(~0u, pre, o);
        if (lane >= o) pre += x;
    }
    int total = __shfl_sync(~0u, pre, 31);
    unsigned acc = 0u;
    if (total <= LIST_CAP) {
        int k = pre - c;
        unsigned tmp = w;
        while (tmp) {
            int b = __ffs(tmp) - 1; tmp &= tmp - 1;
            lists[warp][k++] = (unsigned short)(lane * 32 + b);
        }
        __syncwarp();
        int j = 0;
        for (; j + 4 <= total; j += 4) {
            int i0 = lists[warp][j],     i1 = lists[warp][j + 1];
            int i2 = lists[warp][j + 2], i3 = lists[warp][j + 3];
            acc |= g_adj[i0 * 32 + lane] | g_adj[i1 * 32 + lane]
                 | g_adj[i2 * 32 + lane] | g_adj[i3 * 32 + lane];
        }
        for (; j < total; j++) acc |= g_adj[lists[warp][j] * 32 + lane];
    } else {   // essentially-impossible fallback
        for (int ww = 0; ww < 32; ww++) {
            unsigned word = __shfl_sync(~0u, w, ww);
            while (word) {
                int b = __ffs(word) - 1; word &= word - 1;
                acc |= g_adj[(ww * 32 + b) * 32 + lane];
            }
        }
    }
    out[row * 32 + lane] = w & acc;
}

// topo bias only depends on path bit in {0,1}: table [2][8]
__global__ void ttab_kernel(const float* __restrict__ w1, const float* __restrict__ b1,
                            const float* __restrict__ w2, const float* __restrict__ b2) {
    int t = threadIdx.x;
    if (t < 16) {
        float pv = (float)(t >> 3);
        int h = t & 7;
        float acc = b2[h];
        for (int c = 0; c < 32; c++) {
            float hv = fmaf(pv, w1[c], b1[c]);
            float s = __fdividef(hv, 1.f + __expf(-hv));
            acc = fmaf(s, w2[c * 8 + h], acc);
        }
        g_ttab[t] = acc;
    }
}

// geo MLP lookup table over dist in [0, TBL_MAX]
__global__ void geo_table_kernel(const float* __restrict__ w1, const float* __restrict__ b1,
                                 const float* __restrict__ w2, const float* __restrict__ b2) {
    int i = blockIdx.x * 256 + threadIdx.x;
    if (i >= TBL_N) return;
    float dist = (float)i * (TBL_MAX / (float)(TBL_N - 1));
    float a[8];
#pragma unroll
    for (int h = 0; h < 8; h++) a[h] = b2[h];
    for (int c = 0; c < 32; c++) {
        float hv = fmaf(dist, w1[c], b1[c]);
        float s = __fdividef(hv, 1.f + __expf(-hv));
#pragma unroll
        for (int h = 0; h < 8; h++) a[h] = fmaf(s, w2[c * 8 + h], a[h]);
    }
#pragma unroll
    for (int h = 0; h < 8; h++) g_tbl[i * 8 + h] = a[h];
}

// ---------------- shared 64x64 tiled SGEMM body, C = [A0|A1]@B + bias [,silu] -
__device__ __forceinline__ void gemm_body(
    const float* __restrict__ A0, const float* __restrict__ A1, int ksplit,
    int lda, const float* __restrict__ B, int ldb,
    const float* __restrict__ bias, float* __restrict__ C, int ldc, int K, int act)
{
    __shared__ float As[16][68];
    __shared__ float Bs[16][64];
    int tid = threadIdx.x;
    int tx = tid & 15, ty = tid >> 4;
    int row0 = blockIdx.y * 64, col0 = blockIdx.x * 64;
    float acc[4][4];
#pragma unroll
    for (int i = 0; i < 4; i++)
#pragma unroll
        for (int j = 0; j < 4; j++) acc[i][j] = 0.f;
    int ar = tid >> 2, ac = (tid & 3) << 2;
    int bk = tid >> 4, bn = (tid & 15) << 2;
    for (int k0 = 0; k0 < K; k0 += 16) {
        const float* Ap = (k0 < ksplit)
            ? &A0[(row0 + ar) * lda + k0 + ac]
            : &A1[(row0 + ar) * lda + (k0 - ksplit) + ac];
        float4 av = *(const float4*)Ap;
        As[ac + 0][ar] = av.x; As[ac + 1][ar] = av.y;
        As[ac + 2][ar] = av.z; As[ac + 3][ar] = av.w;
        *(float4*)&Bs[bk][bn] = *(const float4*)&B[(k0 + bk) * ldb + col0 + bn];
        __syncthreads();
#pragma unroll
        for (int kk = 0; kk < 16; kk++) {
            float4 a = *(const float4*)&As[kk][ty << 2];
            float4 b = *(const float4*)&Bs[kk][tx << 2];
            acc[0][0] = fmaf(a.x, b.x, acc[0][0]); acc[0][1] = fmaf(a.x, b.y, acc[0][1]);
            acc[0][2] = fmaf(a.x, b.z, acc[0][2]); acc[0][3] = fmaf(a.x, b.w, acc[0][3]);
            acc[1][0] = fmaf(a.y, b.x, acc[1][0]); acc[1][1] = fmaf(a.y, b.y, acc[1][1]);
            acc[1][2] = fmaf(a.y, b.z, acc[1][2]); acc[1][3] = fmaf(a.y, b.w, acc[1][3]);
            acc[2][0] = fmaf(a.z, b.x, acc[2][0]); acc[2][1] = fmaf(a.z, b.y, acc[2][1]);
            acc[2][2] = fmaf(a.z, b.z, acc[2][2]); acc[2][3] = fmaf(a.z, b.w, acc[2][3]);
            acc[3][0] = fmaf(a.w, b.x, acc[3][0]); acc[3][1] = fmaf(a.w, b.y, acc[3][1]);
            acc[3][2] = fmaf(a.w, b.z, acc[3][2]); acc[3][3] = fmaf(a.w, b.w, acc[3][3]);
        }
        __syncthreads();
    }
#pragma unroll
    for (int i = 0; i < 4; i++) {
        int r = row0 + (ty << 2) + i;
#pragma unroll
        for (int j = 0; j < 4; j++) {
            int cc = col0 + (tx << 2) + j;
            float v = acc[i][j] + bias[cc];
            if (act) v = __fdividef(v, 1.f + __expf(-v));
            C[r * ldc + cc] = v;
        }
    }
}

__global__ __launch_bounds__(256) void sgemm64(
    const float* __restrict__ A0, const float* __restrict__ A1, int ksplit,
    int lda, const float* __restrict__ B, int ldb,
    const float* __restrict__ bias, float* __restrict__ C, int ldc, int K, int act)
{
    gemm_body(A0, A1, ksplit, lda, B, ldb, bias, C, ldc, K, act);
}

// q/k/v projections fused in one launch via blockIdx.z
__global__ __launch_bounds__(256) void qkv_kernel(
    const float* __restrict__ src, const float* __restrict__ tgt,
    const float* __restrict__ Wq, const float* __restrict__ bq,
    const float* __restrict__ Wk, const float* __restrict__ bk,
    const float* __restrict__ Wv, const float* __restrict__ bv)
{
    int z = blockIdx.z;
    const float* A = (z == 0) ? src : tgt;
    const float* W = (z == 0) ? Wq : ((z == 1) ? Wk : Wv);
    const float* b = (z == 0) ? bq : ((z == 1) ? bk : bv);
    float* C = (z == 0) ? g_q : ((z == 1) ? g_k : g_v);
    gemm_body(A, A, 256, 256, W, 256, b, C, 256, 256, 0);
}

// gate logits: 2 dots of length 1024 per node, then 2-way softmax
__global__ __launch_bounds__(256) void gate2_kernel(const float* __restrict__ w2,
                                                    const float* __restrict__ b2) {
    int n = blockIdx.x, tid = threadIdx.x;
    const float* hrow = g_gateh + n * 1024;
    float s0 = 0.f, s1 = 0.f;
#pragma unroll
    for (int t = 0; t < 4; t++) {
        int j = tid + 256 * t;
        float hv = hrow[j];
        s0 = fmaf(hv, w2[j * 2 + 0], s0);
        s1 = fmaf(hv, w2[j * 2 + 1], s1);
    }
    for (int o = 16; o; o >>= 1) {
        s0 += __shfl_xor_sync(~0u, s0, o);
        s1 += __shfl_xor_sync(~0u, s1, o);
    }
    __shared__ float r0[8], r1[8];
    if ((tid & 31) == 0) { r0[tid >> 5] = s0; r1[tid >> 5] = s1; }
    __syncthreads();
    if (tid == 0) {
        float l0 = b2[0], l1 = b2[1];
        for (int j = 0; j < 8; j++) { l0 += r0[j]; l1 += r1[j]; }
        float m = fmaxf(l0, l1);
        float e0 = __expf(l0 - m), e1 = __expf(l1 - m);
        float inv = __fdividef(1.f, e0 + e1);
        g_gate[n * 2 + 0] = e0 * inv;
        g_gate[n * 2 + 1] = e1 * inv;
    }
}

// ---------------- fused logits: QK/sqrt(D) + gate0*geoTbl(dist) + gate1*topo -
#define QPAD 260
#define LOGITS_SMEM ((64 * QPAD + 320) * 4)

__global__ __launch_bounds__(256) void logits_kernel(const float* __restrict__ pos)
{
    extern __shared__ float sh[];
    float* qs  = sh;                       // 32 x 260
    float* ks  = sh + 32 * QPAD;           // 32 x 260
    float* ext = sh + 64 * QPAD;
    float* sg0 = ext;                      // 32
    float* sg1 = sg0 + 32;                 // 32
    float* spn = sg1 + 32;                 // 32*3
    float* spm = spn + 96;                 // 32*3
    float* stt = spm + 96;                 // 16
    unsigned* spw = (unsigned*)(stt + 16); // 32

    int tid = threadIdx.x;
    int m0 = blockIdx.x * 32, n0 = blockIdx.y * 32;

#pragma unroll
    for (int t = 0; t < 8; t++) {
        int lin = tid + 256 * t;
        int r = lin >> 6, c4 = (lin & 63) << 2;
        *(float4*)&qs[r * QPAD + c4] = *(const float4*)&g_q[(n0 + r) * 256 + c4];
        *(float4*)&ks[r * QPAD + c4] = *(const float4*)&g_k[(m0 + r) * 256 + c4];
    }
    if (tid < 32) {
        sg0[tid] = g_gate[(n0 + tid) * 2 + 0];
        sg1[tid] = g_gate[(n0 + tid) * 2 + 1];
        spw[tid] = g_pa[(n0 + tid) * 32 + blockIdx.x];
        spn[tid * 3 + 0] = pos[(n0 + tid) * 3 + 0];
        spn[tid * 3 + 1] = pos[(n0 + tid) * 3 + 1];
        spn[tid * 3 + 2] = pos[(n0 + tid) * 3 + 2];
        spm[tid * 3 + 0] = pos[(m0 + tid) * 3 + 0];
        spm[tid * 3 + 1] = pos[(m0 + tid) * 3 + 1];
        spm[tid * 3 + 2] = pos[(m0 + tid) * 3 + 2];
    }
    if (tid < 16) stt[tid] = g_ttab[tid];
    __syncthreads();

    int mi = tid & 31, nbase = tid >> 5;
    float res[4][8];
    float px = spm[mi * 3 + 0], py = spm[mi * 3 + 1], pz = spm[mi * 3 + 2];

#pragma unroll
    for (int i = 0; i < 4; i++) {
        int ni = nbase + 8 * i;
        float dx = spn[ni * 3 + 0] - px;
        float dy = spn[ni * 3 + 1] - py;
        float dz = spn[ni * 3 + 2] - pz;
        float dist = sqrtf(fmaxf(dx * dx + dy * dy + dz * dz, 1e-12f));
        float gv0 = sg0[ni], gv1 = sg1[ni];
        int bit = (spw[ni] >> mi) & 1;

        float t = fminf(dist, TBL_MAX) * TBL_SCALE;
        int i0 = (int)t;
        if (i0 > TBL_N - 2) i0 = TBL_N - 2;
        float fr = t - (float)i0;
        const float4* tb = (const float4*)&g_tbl[i0 * 8];
        float4 r0 = __ldg(tb + 0), r1 = __ldg(tb + 1);
        float4 r2 = __ldg(tb + 2), r3 = __ldg(tb + 3);
        float a[8];
        a[0] = r0.x + fr * (r2.x - r0.x); a[1] = r0.y + fr * (r2.y - r0.y);
        a[2] = r0.z + fr * (r2.z - r0.z); a[3] = r0.w + fr * (r2.w - r0.w);
        a[4] = r1.x + fr * (r3.x - r1.x); a[5] = r1.y + fr * (r3.y - r1.y);
        a[6] = r1.z + fr * (r3.z - r1.z); a[7] = r1.w + fr * (r3.w - r1.w);
#pragma unroll
        for (int h = 0; h < 8; h++)
            res[i][h] = gv0 * a[h] + gv1 * stt[bit * 8 + h];
    }

    const float scale = 0.17677669529663687f;   // 1/sqrt(32)
#pragma unroll
    for (int h = 0; h < 8; h++) {
        float4 kr[8];
#pragma unroll
        for (int j = 0; j < 8; j++)
            kr[j] = *(const float4*)&ks[mi * QPAD + h * 32 + j * 4];
#pragma unroll
        for (int i = 0; i < 4; i++) {
            int ni = nbase + 8 * i;
            float s = 0.f;
#pragma unroll
            for (int j = 0; j < 8; j++) {
                float4 qv = *(const float4*)&qs[ni * QPAD + h * 32 + j * 4];
                s += qv.x * kr[j].x + qv.y * kr[j].y + qv.z * kr[j].z + qv.w * kr[j].w;
            }
            res[i][h] = fmaf(s, scale, res[i][h]);
        }
    }

#pragma unroll
    for (int i = 0; i < 4; i++) {
        int ng = n0 + nbase + 8 * i;
#pragma unroll
        for (int h = 0; h < 8; h++)
            g_logits[(ng * 8 + h) * 1024 + m0 + mi] = res[i][h];
    }
}

// ---------------- row stats (max, 1/sum of exp) -------------------------------
__global__ __launch_bounds__(256) void stats_kernel() {
    int row = blockIdx.x;
    const float* p = g_logits + (long)row * 1024;
    int tid = threadIdx.x;
    float4 v = *(const float4*)&p[tid * 4];
    float mx = fmaxf(fmaxf(v.x, v.y), fmaxf(v.z, v.w));
    for (int o = 16; o; o >>= 1) mx = fmaxf(mx, __shfl_xor_sync(~0u, mx, o));
    __shared__ float rm[8], rs[8];
    if ((tid & 31) == 0) rm[tid >> 5] = mx;
    __syncthreads();
    mx = rm[0];
#pragma unroll
    for (int j = 1; j < 8; j++) mx = fmaxf(mx, rm[j]);
    float s = __expf(v.x - mx) + __expf(v.y - mx) + __expf(v.z - mx) + __expf(v.w - mx);
    for (int o = 16; o; o >>= 1) s += __shfl_xor_sync(~0u, s, o);
    if ((tid & 31) == 0) rs[tid >> 5] = s;
    __syncthreads();
    if (tid == 0) {
        float tot = 0.f;
#pragma unroll
        for (int j = 0; j < 8; j++) tot += rs[j];
        g_stats[row] = make_float2(mx, __fdividef(1.f, tot));
    }
}

// ---------------- PV with inline softmax: out[n,h*32+d] = sum_m p[n,h,m] v[m,h*32+d]
__global__ __launch_bounds__(256) void pv_kernel() {
    int h = blockIdx.x, n0 = blockIdx.y * 64;
    __shared__ float As[64][36];   // n x m (softmaxed probs)
    __shared__ float Bs[32][32];   // m x d
    __shared__ float2 sstat[64];
    int tid = threadIdx.x;
    int dxi = tid & 31;
    int ty = tid >> 5;
    if (tid < 64) sstat[tid] = g_stats[(n0 + tid) * 8 + h];
    __syncthreads();
    float acc[8];
#pragma unroll
    for (int i = 0; i < 8; i++) acc[i] = 0.f;

    for (int m0 = 0; m0 < 1024; m0 += 32) {
#pragma unroll
        for (int t = 0; t < 2; t++) {
            int lin = tid + 256 * t;
            int r = lin >> 3, c4 = (lin & 7) << 2;
            float4 v = *(const float4*)&g_logits[((long)(n0 + r) * 8 + h) * 1024 + m0 + c4];
            float2 st = sstat[r];
            v.x = __expf(v.x - st.x) * st.y;
            v.y = __expf(v.y - st.x) * st.y;
            v.z = __expf(v.z - st.x) * st.y;
            v.w = __expf(v.w - st.x) * st.y;
            *(float4*)&As[r][c4] = v;
        }
        {
            int r = tid >> 3, c4 = (tid & 7) << 2;
            *(float4*)&Bs[r][c4] = *(const float4*)&g_v[(m0 + r) * 256 + h * 32 + c4];
        }
        __syncthreads();
#pragma unroll
        for (int mm = 0; mm < 32; mm += 4) {
            float b0 = Bs[mm + 0][dxi], b1 = Bs[mm + 1][dxi];
            float b2 = Bs[mm + 2][dxi], b3 = Bs[mm + 3][dxi];
#pragma unroll
            for (int i = 0; i < 8; i++) {
                float4 a = *(const float4*)&As[ty + 8 * i][mm];
                acc[i] = fmaf(a.x, b0, fmaf(a.y, b1, fmaf(a.z, b2, fmaf(a.w, b3, acc[i]))));
            }
        }
        __syncthreads();
    }
#pragma unroll
    for (int i = 0; i < 8; i++)
        g_attnout[(n0 + ty + 8 * i) * 256 + h * 32 + dxi] = acc[i];
}

// ---------------- residual + layernorm ----------------------------------------
__global__ __launch_bounds__(256) void ln_kernel(const float* __restrict__ src,
                                                 const float* __restrict__ g,
                                                 const float* __restrict__ b,
                                                 float* __restrict__ out) {
    int n = blockIdx.x, tid = threadIdx.x;
    float x = src[n * 256 + tid] + g_proj[n * 256 + tid];
    float s = x;
    for (int o = 16; o; o >>= 1) s += __shfl_xor_sync(~0u, s, o);
    __shared__ float r1[8], r2[8];
    if ((tid & 31) == 0) r1[tid >> 5] = s;
    __syncthreads();
    float tot = 0.f;
#pragma unroll
    for (int j = 0; j < 8; j++) tot += r1[j];
    float mu = tot * (1.f / 256.f);
    float d = x - mu;
    float s2 = d * d;
    for (int o = 16; o; o >>= 1) s2 += __shfl_xor_sync(~0u, s2, o);
    if ((tid & 31) == 0) r2[tid >> 5] = s2;
    __syncthreads();
    float var = 0.f;
#pragma unroll
    for (int j = 0; j < 8; j++) var += r2[j];
    var *= (1.f / 256.f);
    out[n * 256 + tid] = d * rsqrtf(var + 1e-5f) * g[tid] + b[tid];
}

// ---------------- launch ------------------------------------------------------
extern "C" void kernel_launch(void* const* d_in, const int* in_sizes, int n_in,
                              void* d_out, int out_size) {
    const float* src_feat = (const float*)d_in[0];
    const float* tgt_feat = (const float*)d_in[1];
    const float* src_pos  = (const float*)d_in[2];
    const void*  edges    = d_in[3];
    const float* Wq = (const float*)d_in[4],  *bq = (const float*)d_in[5];
    const float* Wk = (const float*)d_in[6],  *bk = (const float*)d_in[7];
    const float* Wv = (const float*)d_in[8],  *bv = (const float*)d_in[9];
    const float* geo_w1 = (const float*)d_in[10], *geo_b1 = (const float*)d_in[11];
    const float* geo_w2 = (const float*)d_in[12], *geo_b2 = (const float*)d_in[13];
    const float* top_w1 = (const float*)d_in[14], *top_b1 = (const float*)d_in[15];
    const float* top_w2 = (const float*)d_in[16], *top_b2 = (const float*)d_in[17];
    const float* gate_w1 = (const float*)d_in[18], *gate_b1 = (const float*)d_in[19];
    const float* gate_w2 = (const float*)d_in[20], *gate_b2 = (const float*)d_in[21];
    const float* Wo = (const float*)d_in[22], *bo = (const float*)d_in[23];
    const float* ln_g = (const float*)d_in[24], *ln_b = (const float*)d_in[25];
    float* out = (float*)d_out;

    void *pgateh, *pattn, *pproj;
    cudaGetSymbolAddress(&pgateh, g_gateh);
    cudaGetSymbolAddress(&pattn, g_attnout);
    cudaGetSymbolAddress(&pproj, g_proj);

    cudaFuncSetAttribute(logits_kernel,
                         cudaFuncAttributeMaxDynamicSharedMemorySize, LOGITS_SMEM);

    // adjacency / path propagation (binary bitsets)
    detect_kernel<<<1, 1>>>((const unsigned*)edges);
    zero_adj_kernel<<<128, 256>>>();
    scatter_edges_kernel<<<64, 256>>>(edges);
    path_round_kernel<<<128, 256>>>(0);
    path_round_kernel<<<128, 256>>>(1);
    path_round_kernel<<<128, 256>>>(2);   // final path in g_pa
    ttab_kernel<<<1, 16>>>(top_w1, top_b1, top_w2, top_b2);
    geo_table_kernel<<<32, 256>>>(geo_w1, geo_b1, geo_w2, geo_b2);

    // q/k/v projections (single wave)
    qkv_kernel<<<dim3(4, 16, 3), 256>>>(src_feat, tgt_feat, Wq, bq, Wk, bk, Wv, bv);

    // gate MLP (split-K concat folded into GEMM)
    sgemm64<<<dim3(16, 16), 256>>>(src_feat, tgt_feat, 256, 256, gate_w1, 1024,
                                   gate_b1, (float*)pgateh, 1024, 512, 1);
    gate2_kernel<<<1024, 256>>>(gate_w2, gate_b2);

    // fused QK + geo + topo logits, row stats, PV with inline softmax
    logits_kernel<<<dim3(32, 32), 256, LOGITS_SMEM>>>(src_pos);
    stats_kernel<<<8192, 256>>>();
    pv_kernel<<<dim3(8, 16), 256>>>();

    // output projection + residual + layernorm
    sgemm64<<<dim3(4, 16), 256>>>((const float*)pattn, (const float*)pattn, 256, 256,
                                  Wo, 256, bo, (float*)pproj, 256, 256, 0);
    ln_kernel<<<1024, 256>>>(src_feat, ln_g, ln_b, out);
}